// round 16
// baseline (speedup 1.0000x reference)
#include <cuda_runtime.h>
#include <cuda_fp16.h>
#include <cstdint>

#define BB 2
#define SS 2048
#define NH 16
#define HD 64
#define HID 1024

typedef __half hf;

// ---------------- HMMA m16n8k16 fp16 ----------------
__device__ __forceinline__ void mma16816(float* c, const uint32_t* a, const uint32_t* b) {
    asm volatile("mma.sync.aligned.m16n8k16.row.col.f32.f16.f16.f32 "
                 "{%0,%1,%2,%3}, {%4,%5,%6,%7}, {%8,%9}, {%0,%1,%2,%3};"
                 : "+f"(c[0]), "+f"(c[1]), "+f"(c[2]), "+f"(c[3])
                 : "r"(a[0]), "r"(a[1]), "r"(a[2]), "r"(a[3]), "r"(b[0]), "r"(b[1]));
}

// ldmatrix x4 (and transposing variant)
__device__ __forceinline__ void ldsm4(uint32_t& r0, uint32_t& r1, uint32_t& r2, uint32_t& r3,
                                      uint32_t addr) {
    asm volatile("ldmatrix.sync.aligned.m8n8.x4.shared.b16 {%0,%1,%2,%3}, [%4];"
                 : "=r"(r0), "=r"(r1), "=r"(r2), "=r"(r3) : "r"(addr));
}
__device__ __forceinline__ void ldsm4t(uint32_t& r0, uint32_t& r1, uint32_t& r2, uint32_t& r3,
                                       uint32_t addr) {
    asm volatile("ldmatrix.sync.aligned.m8n8.x4.trans.shared.b16 {%0,%1,%2,%3}, [%4];"
                 : "=r"(r0), "=r"(r1), "=r"(r2), "=r"(r3) : "r"(addr));
}

__device__ __forceinline__ uint32_t round_pair_h(float v0, float v1) {
    __half2 h = __float22half2_rn(make_float2(v0, v1));
    return *(uint32_t*)&h;
}

// ---------------- cp.async helpers ----------------
__device__ __forceinline__ uint32_t smem_u32(const void* p) {
    return (uint32_t)__cvta_generic_to_shared(p);
}
__device__ __forceinline__ void cp16(uint32_t dst, const void* src) {
    asm volatile("cp.async.cg.shared.global [%0], [%1], 16;" :: "r"(dst), "l"(src));
}
#define CP_COMMIT() asm volatile("cp.async.commit_group;" ::: "memory")
#define CP_WAIT0()  asm volatile("cp.async.wait_group 0;" ::: "memory")
#define CP_WAIT1()  asm volatile("cp.async.wait_group 1;" ::: "memory")

// ---------------- scratch (referenced ONLY inside kernels) ----------------
__device__ __align__(16) hf g_xh[4096 * 1024];
__device__ __align__(16) hf g_wqh[3072 * 1024];
__device__ __align__(16) hf g_woh[1024 * 1024];
__device__ __align__(16) hf g_qh[32 * 2048 * 64];   // q rounded, *1/8  [bh][s][d]
__device__ __align__(16) hf g_kh[32 * 2048 * 64];   // k rounded       [bh][s][d]
__device__ __align__(16) hf g_vh[32 * 2048 * 64];   // v rounded       [bh][s][d]
__device__ __align__(16) hf g_ah[4096 * 1024];

// ---------------- fused prep kernel ----------------
__global__ void prep_all(const float* __restrict__ x, const float* __restrict__ qkv_w,
                         const float* __restrict__ out_w) {
    int bid = blockIdx.x, tid = threadIdx.x;
    if (bid < 4096) {
        int i = bid * 256 + tid;
        float4 v = ((const float4*)x)[i];
        ((uint32_t*)g_xh)[i * 2]     = round_pair_h(v.x, v.y);
        ((uint32_t*)g_xh)[i * 2 + 1] = round_pair_h(v.z, v.w);
        return;
    }
    __shared__ float t[32][33];
    const float* src; hf* dst; int R = 1024, C, bx, by;
    if (bid < 7168) { src = qkv_w; dst = g_wqh; C = 3072; int b2 = bid - 4096; bx = b2 % 96; by = b2 / 96; }
    else            { src = out_w; dst = g_woh; C = 1024; int b2 = bid - 7168; bx = b2 % 32; by = b2 / 32; }
    int c0 = bx * 32, r0 = by * 32;
    int xx = tid & 31, yy = tid >> 5;
#pragma unroll
    for (int j = 0; j < 32; j += 8)
        t[yy + j][xx] = src[(size_t)(r0 + yy + j) * C + c0 + xx];
    __syncthreads();
#pragma unroll
    for (int j = 0; j < 32; j += 8) {
        size_t o = (size_t)(c0 + yy + j) * R + r0 + xx;
        dst[o] = __float2half_rn(t[xx][yy + j]);
    }
}

// =====================================================================
// HMMA GEMM: 3-stage cp.async + ldmatrix, fp16 1-term, 3 CTAs/SM forced.
// =====================================================================
#define GARR 5120
#define GSTG (2 * GARR)
#define GEMM_SMEM (3 * GSTG * 2)   // 61440 bytes -> 3 CTAs = 184320 <= 228KB

__global__ void __launch_bounds__(256, 3) hmma_gemm(const float* __restrict__ bias,
                                                    float* __restrict__ C, int mode) {
    extern __shared__ __align__(16) hf dsm[];
    const int tid = threadIdx.x, wid = tid >> 5, lane = tid & 31;
    const int g = lane >> 2, t2 = (lane & 3) * 2;
    const int wy = wid & 1, wx = wid >> 1;
    const int bm = blockIdx.y * 128, bn = blockIdx.x * 128;

    const int rA = (lane & 7) + ((lane >> 3) & 1) * 8;
    const int kA = (lane >> 4) * 8;
    const int rB = (lane & 7) + (lane >> 4) * 8;
    const int kB = ((lane >> 3) & 1) * 8;

    const hf* Ah = (mode == 0) ? g_xh : g_ah;
    const hf* Bh = (mode == 0) ? g_wqh : g_woh;

    auto issueG = [&](int ch, int s) {
        int k0 = ch * 32;
        hf* base = dsm + s * GSTG;
#pragma unroll
        for (int t = 0; t < 2; t++) {
            int idx = tid + t * 256;
            int row = idx >> 2, c = (idx & 3) * 8;
            uint32_t d0 = smem_u32(base + row * 40 + c);
            cp16(d0,            &Ah[(size_t)(bm + row) * 1024 + k0 + c]);
            cp16(d0 + GARR * 2, &Bh[(size_t)(bn + row) * 1024 + k0 + c]);
        }
        CP_COMMIT();
    };

    float acc[4][4][4];
#pragma unroll
    for (int i = 0; i < 4; i++)
#pragma unroll
        for (int j = 0; j < 4; j++)
#pragma unroll
            for (int r = 0; r < 4; r++) acc[i][j][r] = 0.f;

    issueG(0, 0);
    issueG(1, 1);
    for (int ch = 0; ch < 32; ch++) {
        if (ch == 31) { CP_WAIT0(); } else { CP_WAIT1(); }
        __syncthreads();
        if (ch + 2 < 32) issueG(ch + 2, (ch + 2) % 3);

        hf* sAh = dsm + (ch % 3) * GSTG;
        hf* sBh = sAh + GARR;
#pragma unroll
        for (int kk = 0; kk < 2; kk++) {
            int kc = kk * 16;
            uint32_t ah[4][4];
#pragma unroll
            for (int mf = 0; mf < 4; mf++) {
                int m0 = wy * 64 + mf * 16;
                ldsm4(ah[mf][0], ah[mf][1], ah[mf][2], ah[mf][3],
                      smem_u32(&sAh[(m0 + rA) * 40 + kc + kA]));
            }
            uint32_t bhf[4][2];
#pragma unroll
            for (int p = 0; p < 2; p++) {
                int n0 = wx * 32 + p * 16;
                ldsm4(bhf[2 * p][0], bhf[2 * p][1], bhf[2 * p + 1][0], bhf[2 * p + 1][1],
                      smem_u32(&sBh[(n0 + rB) * 40 + kc + kB]));
            }
#pragma unroll
            for (int nf = 0; nf < 4; nf++)
#pragma unroll
                for (int mf = 0; mf < 4; mf++)
                    mma16816(acc[mf][nf], ah[mf], bhf[nf]);
        }
    }

    // ---- epilogue ----
#pragma unroll
    for (int mf = 0; mf < 4; mf++) {
#pragma unroll
        for (int nf = 0; nf < 4; nf++) {
            int m = bm + wy * 64 + mf * 16 + g;
            int n = bn + wx * 32 + nf * 8 + t2;
            float bv0 = bias[n], bv1 = bias[n + 1];
#pragma unroll
            for (int half = 0; half < 2; half++) {
                int mm = m + half * 8;
                float v0 = acc[mf][nf][half * 2] + bv0;
                float v1 = acc[mf][nf][half * 2 + 1] + bv1;
                if (mode == 1) {
                    *(float2*)&C[(size_t)mm * HID + n] = make_float2(v0, v1);
                } else {
                    int b = mm >> 11, s = mm & (SS - 1);
                    int h = n / 192, r = n % 192;
                    size_t base = ((size_t)(b * NH + h) * SS + s) * HD;
                    if (r < 64) {
                        *(uint32_t*)&g_qh[base + r] = round_pair_h(v0 * 0.125f, v1 * 0.125f);
                    } else if (r < 128) {
                        *(uint32_t*)&g_kh[base + (r - 64)] = round_pair_h(v0, v1);
                    } else {
                        *(uint32_t*)&g_vh[base + (r - 128)] = round_pair_h(v0, v1);
                    }
                }
            }
        }
    }
}

// =====================================================================
// HMMA flash attention (exact R14 version): 3-stage KV pipeline,
// fp16 1-term, V via ldmatrix.trans.
// =====================================================================
#define AST 72
#define QARR (128 * AST)
#define KARR (64 * AST)
#define KVSTG (2 * KARR)
#define ATTN_SMEM ((QARR + 3 * KVSTG) * 2)   // 73728 bytes

__global__ void __launch_bounds__(256) attn_hmma() {
    extern __shared__ __align__(16) hf sh[];
    hf* Qh = sh;

    const int tid = threadIdx.x, wid = tid >> 5, lane = tid & 31;
    const int g = lane >> 2, t2 = (lane & 3) * 2;
    const int qt = blockIdx.x, bh = blockIdx.y;

    const int rA = (lane & 7) + ((lane >> 3) & 1) * 8;
    const int kA = (lane >> 4) * 8;
    const int rB = (lane & 7) + (lane >> 4) * 8;
    const int kB = ((lane >> 3) & 1) * 8;
    const int rV = (lane & 7) + ((lane >> 3) & 1) * 8;
    const int cV = (lane >> 4) * 8;

    const hf* Qhg = g_qh + ((size_t)bh * SS + qt * 128) * HD;
    const hf* Khg = g_kh + (size_t)bh * SS * HD;
    const hf* Vhg = g_vh + (size_t)bh * SS * HD;

    auto issueKV = [&](int kt, int s) {
        hf* base = sh + QARR + s * KVSTG;
#pragma unroll
        for (int t = 0; t < 2; t++) {
            int idx = tid + t * 256;
            int row = idx >> 3, c = (idx & 7) * 8;
            uint32_t d0 = smem_u32(base + row * AST + c);
            cp16(d0,            &Khg[(size_t)(kt * 64 + row) * HD + c]);
            cp16(d0 + KARR * 2, &Vhg[(size_t)(kt * 64 + row) * HD + c]);
        }
        CP_COMMIT();
    };

#pragma unroll
    for (int t = 0; t < 4; t++) {
        int idx = tid + t * 256;
        int row = idx >> 3, c = (idx & 7) * 8;
        *(uint4*)&Qh[row * AST + c] = *(const uint4*)&Qhg[row * HD + c];
    }

    float Oacc[8][4];
#pragma unroll
    for (int i = 0; i < 8; i++)
#pragma unroll
        for (int r = 0; r < 4; r++) Oacc[i][r] = 0.f;
    float psum0 = 0.f, psum1 = 0.f;

    issueKV(0, 0);
    issueKV(1, 1);
    const int NT = SS / 64;
    for (int kt = 0; kt < NT; kt++) {
        if (kt == NT - 1) { CP_WAIT0(); } else { CP_WAIT1(); }
        __syncthreads();
        if (kt + 2 < NT) issueKV(kt + 2, (kt + 2) % 3);

        hf* Kh = sh + QARR + (kt % 3) * KVSTG;
        hf* Vh = Kh + KARR;

        // ---- S = Q K^T ----
        float sacc[8][4];
#pragma unroll
        for (int i = 0; i < 8; i++)
#pragma unroll
            for (int r = 0; r < 4; r++) sacc[i][r] = 0.f;
#pragma unroll
        for (int kb = 0; kb < 4; kb++) {
            int kc = kb * 16, m0 = wid * 16;
            uint32_t ah[4];
            ldsm4(ah[0], ah[1], ah[2], ah[3], smem_u32(&Qh[(m0 + rA) * AST + kc + kA]));
            uint32_t kbh[8][2];
#pragma unroll
            for (int p = 0; p < 4; p++)
                ldsm4(kbh[2 * p][0], kbh[2 * p][1], kbh[2 * p + 1][0], kbh[2 * p + 1][1],
                      smem_u32(&Kh[(p * 16 + rB) * AST + kc + kB]));
#pragma unroll
            for (int nf = 0; nf < 8; nf++)
                mma16816(sacc[nf], ah, kbh[nf]);
        }

        // ---- p = exp(s), fp16-round to A-fragments ----
        uint32_t pH[8][2];
#pragma unroll
        for (int nf = 0; nf < 8; nf++) {
            float p0 = __expf(sacc[nf][0]);
            float p1 = __expf(sacc[nf][1]);
            float p2 = __expf(sacc[nf][2]);
            float p3 = __expf(sacc[nf][3]);
            psum0 += p0 + p1;
            psum1 += p2 + p3;
            pH[nf][0] = round_pair_h(p0, p1);
            pH[nf][1] = round_pair_h(p2, p3);
        }

        // ---- O += P V (B-fragments via ldmatrix.trans) ----
#pragma unroll
        for (int kb = 0; kb < 4; kb++) {
            int kc = kb * 16;
            uint32_t ah[4] = { pH[2 * kb][0], pH[2 * kb][1], pH[2 * kb + 1][0], pH[2 * kb + 1][1] };
            uint32_t vhf[8][2];
#pragma unroll
            for (int p = 0; p < 4; p++)
                ldsm4t(vhf[2 * p][0], vhf[2 * p][1], vhf[2 * p + 1][0], vhf[2 * p + 1][1],
                       smem_u32(&Vh[(kc + rV) * AST + p * 16 + cV]));
#pragma unroll
            for (int df = 0; df < 8; df++)
                mma16816(Oacc[df], ah, vhf[df]);
        }
    }

    // ---- epilogue ----
    psum0 += __shfl_xor_sync(0xffffffffu, psum0, 1);
    psum0 += __shfl_xor_sync(0xffffffffu, psum0, 2);
    psum1 += __shfl_xor_sync(0xffffffffu, psum1, 1);
    psum1 += __shfl_xor_sync(0xffffffffu, psum1, 2);
    float inv0 = 1.0f / psum0, inv1 = 1.0f / psum1;

    const int b = bh >> 4, h = bh & 15;
    const int row0 = qt * 128 + wid * 16 + g;
#pragma unroll
    for (int df = 0; df < 8; df++) {
        size_t o0 = ((size_t)b * SS + row0) * HID + h * HD + df * 8 + t2;
        size_t o1 = o0 + (size_t)8 * HID;
        *(uint32_t*)&g_ah[o0] = round_pair_h(Oacc[df][0] * inv0, Oacc[df][1] * inv0);
        *(uint32_t*)&g_ah[o1] = round_pair_h(Oacc[df][2] * inv1, Oacc[df][3] * inv1);
    }
}

// =====================================================================
extern "C" void kernel_launch(void* const* d_in, const int* in_sizes, int n_in,
                              void* d_out, int out_size) {
    const float* x     = (const float*)d_in[0];
    const float* qkv_w = (const float*)d_in[1];
    const float* qkv_b = (const float*)d_in[2];
    const float* out_w = (const float*)d_in[3];
    const float* out_b = (const float*)d_in[4];
    float* out = (float*)d_out;

    cudaFuncSetAttribute(hmma_gemm, cudaFuncAttributeMaxDynamicSharedMemorySize, GEMM_SMEM);
    cudaFuncSetAttribute(attn_hmma, cudaFuncAttributeMaxDynamicSharedMemorySize, ATTN_SMEM);

    prep_all<<<8192, 256>>>(x, qkv_w, out_w);
    hmma_gemm<<<dim3(24, 32), 256, GEMM_SMEM>>>(qkv_b, nullptr, 0);
    attn_hmma<<<dim3(16, 32), 256, ATTN_SMEM>>>();
    hmma_gemm<<<dim3(8, 32), 256, GEMM_SMEM>>>(out_b, out, 1);
}

// round 17
// speedup vs baseline: 1.2171x; 1.2171x over previous
#include <cuda_runtime.h>
#include <cuda_fp16.h>
#include <cstdint>

#define BB 2
#define SS 2048
#define NH 16
#define HD 64
#define HID 1024

typedef __half hf;

// ---------------- HMMA m16n8k16 fp16 ----------------
__device__ __forceinline__ void mma16816(float* c, const uint32_t* a, const uint32_t* b) {
    asm volatile("mma.sync.aligned.m16n8k16.row.col.f32.f16.f16.f32 "
                 "{%0,%1,%2,%3}, {%4,%5,%6,%7}, {%8,%9}, {%0,%1,%2,%3};"
                 : "+f"(c[0]), "+f"(c[1]), "+f"(c[2]), "+f"(c[3])
                 : "r"(a[0]), "r"(a[1]), "r"(a[2]), "r"(a[3]), "r"(b[0]), "r"(b[1]));
}

// ldmatrix x4 (and transposing variant)
__device__ __forceinline__ void ldsm4(uint32_t& r0, uint32_t& r1, uint32_t& r2, uint32_t& r3,
                                      uint32_t addr) {
    asm volatile("ldmatrix.sync.aligned.m8n8.x4.shared.b16 {%0,%1,%2,%3}, [%4];"
                 : "=r"(r0), "=r"(r1), "=r"(r2), "=r"(r3) : "r"(addr));
}
__device__ __forceinline__ void ldsm4t(uint32_t& r0, uint32_t& r1, uint32_t& r2, uint32_t& r3,
                                       uint32_t addr) {
    asm volatile("ldmatrix.sync.aligned.m8n8.x4.trans.shared.b16 {%0,%1,%2,%3}, [%4];"
                 : "=r"(r0), "=r"(r1), "=r"(r2), "=r"(r3) : "r"(addr));
}

__device__ __forceinline__ uint32_t round_pair_h(float v0, float v1) {
    __half2 h = __float22half2_rn(make_float2(v0, v1));
    return *(uint32_t*)&h;
}

// ---------------- cp.async helpers ----------------
__device__ __forceinline__ uint32_t smem_u32(const void* p) {
    return (uint32_t)__cvta_generic_to_shared(p);
}
__device__ __forceinline__ void cp16(uint32_t dst, const void* src) {
    asm volatile("cp.async.cg.shared.global [%0], [%1], 16;" :: "r"(dst), "l"(src));
}
#define CP_COMMIT() asm volatile("cp.async.commit_group;" ::: "memory")
#define CP_WAIT0()  asm volatile("cp.async.wait_group 0;" ::: "memory")
#define CP_WAIT1()  asm volatile("cp.async.wait_group 1;" ::: "memory")

// ---------------- scratch (referenced ONLY inside kernels) ----------------
__device__ __align__(16) hf g_xh[4096 * 1024];                 // x rounded
__device__ __align__(16) hf g_wqh[3072 * 1024];                // qkv_w^T rounded
__device__ __align__(16) hf g_woh[1024 * 1024];                // out_w^T rounded
__device__ __align__(16) hf g_qh[32 * 2048 * 64];              // q rounded, *1/8  [bh][s][d]
__device__ __align__(16) hf g_kh[32 * 2048 * 64];              // k rounded       [bh][s][d]
__device__ __align__(16) hf g_vh[32 * 2048 * 64];              // v rounded       [bh][s][d]
__device__ __align__(16) hf g_ah[4096 * 1024];                 // attn out rounded

// ---------------- fused prep kernel ----------------
// blocks [0, 4096): round x.  [4096, 7168): transpose qkv_w.  [7168, 8192): transpose out_w.
__global__ void prep_all(const float* __restrict__ x, const float* __restrict__ qkv_w,
                         const float* __restrict__ out_w) {
    int bid = blockIdx.x, tid = threadIdx.x;
    if (bid < 4096) {
        int i = bid * 256 + tid;
        float4 v = ((const float4*)x)[i];
        ((uint32_t*)g_xh)[i * 2]     = round_pair_h(v.x, v.y);
        ((uint32_t*)g_xh)[i * 2 + 1] = round_pair_h(v.z, v.w);
        return;
    }
    __shared__ float t[32][33];
    const float* src; hf* dst; int R = 1024, C, bx, by;
    if (bid < 7168) { src = qkv_w; dst = g_wqh; C = 3072; int b2 = bid - 4096; bx = b2 % 96; by = b2 / 96; }
    else            { src = out_w; dst = g_woh; C = 1024; int b2 = bid - 7168; bx = b2 % 32; by = b2 / 32; }
    int c0 = bx * 32, r0 = by * 32;
    int xx = tid & 31, yy = tid >> 5;   // 32 x 8
#pragma unroll
    for (int j = 0; j < 32; j += 8)
        t[yy + j][xx] = src[(size_t)(r0 + yy + j) * C + c0 + xx];
    __syncthreads();
#pragma unroll
    for (int j = 0; j < 32; j += 8) {
        size_t o = (size_t)(c0 + yy + j) * R + r0 + xx;
        dst[o] = __float2half_rn(t[xx][yy + j]);
    }
}

// =====================================================================
// HMMA GEMM: 3-stage cp.async pipeline + ldmatrix, pure fp16 1-term.
// =====================================================================
#define GARR 5120
#define GSTG (2 * GARR)
#define GEMM_SMEM (3 * GSTG * 2)  // 61440 bytes

__global__ void __launch_bounds__(256) hmma_gemm(const float* __restrict__ bias,
                                                 float* __restrict__ C, int mode) {
    extern __shared__ __align__(16) hf dsm[];
    const int tid = threadIdx.x, wid = tid >> 5, lane = tid & 31;
    const int g = lane >> 2, t2 = (lane & 3) * 2;
    const int wy = wid & 1, wx = wid >> 1;
    const int bm = blockIdx.y * 128, bn = blockIdx.x * 128;

    const int rA = (lane & 7) + ((lane >> 3) & 1) * 8;
    const int kA = (lane >> 4) * 8;
    const int rB = (lane & 7) + (lane >> 4) * 8;
    const int kB = ((lane >> 3) & 1) * 8;

    const hf* Ah = (mode == 0) ? g_xh : g_ah;
    const hf* Bh = (mode == 0) ? g_wqh : g_woh;

    auto issueG = [&](int ch, int s) {
        int k0 = ch * 32;
        hf* base = dsm + s * GSTG;
#pragma unroll
        for (int t = 0; t < 2; t++) {
            int idx = tid + t * 256;
            int row = idx >> 2, c = (idx & 3) * 8;
            uint32_t d0 = smem_u32(base + row * 40 + c);
            cp16(d0,            &Ah[(size_t)(bm + row) * 1024 + k0 + c]);
            cp16(d0 + GARR * 2, &Bh[(size_t)(bn + row) * 1024 + k0 + c]);
        }
        CP_COMMIT();
    };

    float acc[4][4][4];
#pragma unroll
    for (int i = 0; i < 4; i++)
#pragma unroll
        for (int j = 0; j < 4; j++)
#pragma unroll
            for (int r = 0; r < 4; r++) acc[i][j][r] = 0.f;

    issueG(0, 0);
    issueG(1, 1);
    for (int ch = 0; ch < 32; ch++) {
        if (ch == 31) { CP_WAIT0(); } else { CP_WAIT1(); }
        __syncthreads();
        if (ch + 2 < 32) issueG(ch + 2, (ch + 2) % 3);

        hf* sAh = dsm + (ch % 3) * GSTG;
        hf* sBh = sAh + GARR;
#pragma unroll
        for (int kk = 0; kk < 2; kk++) {
            int kc = kk * 16;
            uint32_t ah[4][4];
#pragma unroll
            for (int mf = 0; mf < 4; mf++) {
                int m0 = wy * 64 + mf * 16;
                ldsm4(ah[mf][0], ah[mf][1], ah[mf][2], ah[mf][3],
                      smem_u32(&sAh[(m0 + rA) * 40 + kc + kA]));
            }
            uint32_t bhf[4][2];
#pragma unroll
            for (int p = 0; p < 2; p++) {
                int n0 = wx * 32 + p * 16;
                ldsm4(bhf[2 * p][0], bhf[2 * p][1], bhf[2 * p + 1][0], bhf[2 * p + 1][1],
                      smem_u32(&sBh[(n0 + rB) * 40 + kc + kB]));
            }
#pragma unroll
            for (int nf = 0; nf < 4; nf++)
#pragma unroll
                for (int mf = 0; mf < 4; mf++)
                    mma16816(acc[mf][nf], ah[mf], bhf[nf]);
        }
    }

    // ---- epilogue (V row-major: all three branches coalesced) ----
#pragma unroll
    for (int mf = 0; mf < 4; mf++) {
#pragma unroll
        for (int nf = 0; nf < 4; nf++) {
            int m = bm + wy * 64 + mf * 16 + g;
            int n = bn + wx * 32 + nf * 8 + t2;
            float bv0 = bias[n], bv1 = bias[n + 1];
#pragma unroll
            for (int half = 0; half < 2; half++) {
                int mm = m + half * 8;
                float v0 = acc[mf][nf][half * 2] + bv0;
                float v1 = acc[mf][nf][half * 2 + 1] + bv1;
                if (mode == 1) {
                    *(float2*)&C[(size_t)mm * HID + n] = make_float2(v0, v1);
                } else {
                    int b = mm >> 11, s = mm & (SS - 1);
                    int h = n / 192, r = n % 192;
                    size_t base = ((size_t)(b * NH + h) * SS + s) * HD;
                    if (r < 64) {
                        *(uint32_t*)&g_qh[base + r] = round_pair_h(v0 * 0.125f, v1 * 0.125f);
                    } else if (r < 128) {
                        *(uint32_t*)&g_kh[base + (r - 64)] = round_pair_h(v0, v1);
                    } else {
                        *(uint32_t*)&g_vh[base + (r - 128)] = round_pair_h(v0, v1);
                    }
                }
            }
        }
    }
}

// =====================================================================
// HMMA flash attention: 3-stage KV pipeline; V via ldmatrix.trans.
// =====================================================================
#define AST 72
#define QARR (128 * AST)
#define KARR (64 * AST)
#define KVSTG (2 * KARR)
#define ATTN_SMEM ((QARR + 3 * KVSTG) * 2)   // 73728 bytes

__global__ void __launch_bounds__(256) attn_hmma() {
    extern __shared__ __align__(16) hf sh[];
    hf* Qh = sh;

    const int tid = threadIdx.x, wid = tid >> 5, lane = tid & 31;
    const int g = lane >> 2, t2 = (lane & 3) * 2;
    const int qt = blockIdx.x, bh = blockIdx.y;

    const int rA = (lane & 7) + ((lane >> 3) & 1) * 8;
    const int kA = (lane >> 4) * 8;
    const int rB = (lane & 7) + (lane >> 4) * 8;
    const int kB = ((lane >> 3) & 1) * 8;
    // trans-ldmatrix lane coords for V (k-major [s][d] tile): row=k(s), col=n(d)
    const int rV = (lane & 7) + ((lane >> 3) & 1) * 8;
    const int cV = (lane >> 4) * 8;

    const hf* Qhg = g_qh + ((size_t)bh * SS + qt * 128) * HD;
    const hf* Khg = g_kh + (size_t)bh * SS * HD;
    const hf* Vhg = g_vh + (size_t)bh * SS * HD;

    auto issueKV = [&](int kt, int s) {
        hf* base = sh + QARR + s * KVSTG;
#pragma unroll
        for (int t = 0; t < 2; t++) {
            int idx = tid + t * 256;
            int row = idx >> 3, c = (idx & 7) * 8;
            uint32_t d0 = smem_u32(base + row * AST + c);
            cp16(d0,            &Khg[(size_t)(kt * 64 + row) * HD + c]);
            cp16(d0 + KARR * 2, &Vhg[(size_t)(kt * 64 + row) * HD + c]);
        }
        CP_COMMIT();
    };

#pragma unroll
    for (int t = 0; t < 4; t++) {
        int idx = tid + t * 256;
        int row = idx >> 3, c = (idx & 7) * 8;
        *(uint4*)&Qh[row * AST + c] = *(const uint4*)&Qhg[row * HD + c];
    }

    float Oacc[8][4];
#pragma unroll
    for (int i = 0; i < 8; i++)
#pragma unroll
        for (int r = 0; r < 4; r++) Oacc[i][r] = 0.f;
    float psum0 = 0.f, psum1 = 0.f;

    issueKV(0, 0);
    issueKV(1, 1);
    const int NT = SS / 64;
    for (int kt = 0; kt < NT; kt++) {
        if (kt == NT - 1) { CP_WAIT0(); } else { CP_WAIT1(); }
        __syncthreads();
        if (kt + 2 < NT) issueKV(kt + 2, (kt + 2) % 3);

        hf* Kh = sh + QARR + (kt % 3) * KVSTG;
        hf* Vh = Kh + KARR;

        // ---- S = Q K^T ----
        float sacc[8][4];
#pragma unroll
        for (int i = 0; i < 8; i++)
#pragma unroll
            for (int r = 0; r < 4; r++) sacc[i][r] = 0.f;
#pragma unroll
        for (int kb = 0; kb < 4; kb++) {
            int kc = kb * 16, m0 = wid * 16;
            uint32_t ah[4];
            ldsm4(ah[0], ah[1], ah[2], ah[3], smem_u32(&Qh[(m0 + rA) * AST + kc + kA]));
            uint32_t kbh[8][2];
#pragma unroll
            for (int p = 0; p < 4; p++)
                ldsm4(kbh[2 * p][0], kbh[2 * p][1], kbh[2 * p + 1][0], kbh[2 * p + 1][1],
                      smem_u32(&Kh[(p * 16 + rB) * AST + kc + kB]));
#pragma unroll
            for (int nf = 0; nf < 8; nf++)
                mma16816(sacc[nf], ah, kbh[nf]);
        }

        // ---- p = exp(s), fp16-round to A-fragments ----
        uint32_t pH[8][2];
#pragma unroll
        for (int nf = 0; nf < 8; nf++) {
            float p0 = __expf(sacc[nf][0]);
            float p1 = __expf(sacc[nf][1]);
            float p2 = __expf(sacc[nf][2]);
            float p3 = __expf(sacc[nf][3]);
            psum0 += p0 + p1;
            psum1 += p2 + p3;
            pH[nf][0] = round_pair_h(p0, p1);
            pH[nf][1] = round_pair_h(p2, p3);
        }

        // ---- O += P V  (V tile is [s][d]; B-fragments via ldmatrix.trans) ----
#pragma unroll
        for (int kb = 0; kb < 4; kb++) {
            int kc = kb * 16;
            uint32_t ah[4] = { pH[2 * kb][0], pH[2 * kb][1], pH[2 * kb + 1][0], pH[2 * kb + 1][1] };
            uint32_t vhf[8][2];
#pragma unroll
            for (int p = 0; p < 4; p++)
                ldsm4t(vhf[2 * p][0], vhf[2 * p][1], vhf[2 * p + 1][0], vhf[2 * p + 1][1],
                       smem_u32(&Vh[(kc + rV) * AST + p * 16 + cV]));
#pragma unroll
            for (int df = 0; df < 8; df++)
                mma16816(Oacc[df], ah, vhf[df]);
        }
    }

    // ---- epilogue ----
    psum0 += __shfl_xor_sync(0xffffffffu, psum0, 1);
    psum0 += __shfl_xor_sync(0xffffffffu, psum0, 2);
    psum1 += __shfl_xor_sync(0xffffffffu, psum1, 1);
    psum1 += __shfl_xor_sync(0xffffffffu, psum1, 2);
    float inv0 = 1.0f / psum0, inv1 = 1.0f / psum1;

    const int b = bh >> 4, h = bh & 15;
    const int row0 = qt * 128 + wid * 16 + g;
#pragma unroll
    for (int df = 0; df < 8; df++) {
        size_t o0 = ((size_t)b * SS + row0) * HID + h * HD + df * 8 + t2;
        size_t o1 = o0 + (size_t)8 * HID;
        *(uint32_t*)&g_ah[o0] = round_pair_h(Oacc[df][0] * inv0, Oacc[df][1] * inv0);
        *(uint32_t*)&g_ah[o1] = round_pair_h(Oacc[df][2] * inv1, Oacc[df][3] * inv1);
    }
}

// =====================================================================
extern "C" void kernel_launch(void* const* d_in, const int* in_sizes, int n_in,
                              void* d_out, int out_size) {
    const float* x     = (const float*)d_in[0];
    const float* qkv_w = (const float*)d_in[1];
    const float* qkv_b = (const float*)d_in[2];
    const float* out_w = (const float*)d_in[3];
    const float* out_b = (const float*)d_in[4];
    float* out = (float*)d_out;

    cudaFuncSetAttribute(hmma_gemm, cudaFuncAttributeMaxDynamicSharedMemorySize, GEMM_SMEM);
    cudaFuncSetAttribute(attn_hmma, cudaFuncAttributeMaxDynamicSharedMemorySize, ATTN_SMEM);

    prep_all<<<8192, 256>>>(x, qkv_w, out_w);
    hmma_gemm<<<dim3(24, 32), 256, GEMM_SMEM>>>(qkv_b, nullptr, 0);
    attn_hmma<<<dim3(16, 32), 256, ATTN_SMEM>>>();
    hmma_gemm<<<dim3(8, 32), 256, GEMM_SMEM>>>(out_b, out, 1);
}